// round 11
// baseline (speedup 1.0000x reference)
#include <cuda_runtime.h>
#include <math.h>

#define CN 64
#define CC 64
#define CT 300
#define CV 25
#define TVN 7500
#define ICN 16
#define EPSBN 1e-5f

typedef unsigned long long ull;

__device__ __forceinline__ ull ffma2(ull a, ull b, ull c) {
  ull d;
  asm("fma.rn.f32x2 %0, %1, %2, %3;" : "=l"(d) : "l"(a), "l"(b), "l"(c));
  return d;
}
__device__ __forceinline__ ull pack2(float lo, float hi) {
  ull d;
  asm("mov.b64 %0, {%1, %2};" : "=l"(d) : "f"(lo), "f"(hi));
  return d;
}
__device__ __forceinline__ void unpack2(ull v, float& lo, float& hi) {
  asm("mov.b64 {%0, %1}, %2;" : "=f"(lo), "=f"(hi) : "l"(v));
}

static const int OFF_FA = 0;          // 23,040,000
static const int OFF_FB = 23040000;   // 23,040,000
static const int OFF_S  = 46080000;   // 120,000
static const int OFF_Z  = 46200000;   // yt (30,720,000 used)
static const int OFF_YG = 138360000;  // 30,720,000
static const int OFF_W  = 169080000;  // transposed weights
__device__ float g_scratch[169140000];
__device__ float g_ps1[204800];   // zyg stats partials: [o][3200]
__device__ float g_ps2[204800];
__device__ float g_pt1[122880];   // tcn stats partials: [o][1920]
__device__ float g_pt2[122880];
__device__ float g_bnA[64];
__device__ float g_bnB[64];

// ---------------------------------------------------------------------------
// K0: weight transposes for coalesced tile loads
// ---------------------------------------------------------------------------
__global__ void k_prep(const float* __restrict__ Wa, const float* __restrict__ Wb,
                       const float* __restrict__ Wd, const float* __restrict__ Wt,
                       float* __restrict__ wout) {
  int idx = blockIdx.x * 256 + threadIdx.x;
  if (idx < 6144) {
    int c = idx / 96, row = idx - c * 96;
    wout[idx] = (row < 48) ? Wa[row * 64 + c] : Wb[(row - 48) * 64 + c];
  } else if (idx < 6144 + 12288) {
    int j = idx - 6144;
    int o = j & 63, kc = j >> 6;
    int k = kc >> 6, c = kc & 63;
    wout[idx] = Wd[k * 4096 + o * 64 + c];
  } else if (idx < 55296) {
    int j = idx - 18432;
    int o = j & 63, cdt = j >> 6;
    wout[idx] = Wt[o * 576 + cdt];
  }
}

// ---------------------------------------------------------------------------
// K1: fa/fb GEMM 96x64x128 per block; f32x2 packed column pairs
// ---------------------------------------------------------------------------
__global__ __launch_bounds__(384) void k_fafb(
    const float* __restrict__ x, const float* __restrict__ wabT,
    const float* __restrict__ ba, const float* __restrict__ bb,
    float* __restrict__ fa, float* __restrict__ fb) {
  __shared__ __align__(16) float WS[64 * 96];
  __shared__ __align__(16) float xs[64 * 128];
  int n = blockIdx.y, col0 = blockIdx.x * 128;
  int tid = threadIdx.x;
  for (int m = tid; m < 6144; m += 384) WS[m] = wabT[m];
  const float* xp = x + n * (CC * TVN);
  for (int m = tid; m < 8192; m += 384) {
    int c = m >> 7, col = m & 127;
    int g = col0 + col;
    xs[m] = (g < TVN) ? xp[c * TVN + g] : 0.f;
  }
  __syncthreads();
  int ty = tid >> 4, tx = tid & 15;  // 24 x 16
  ull acc[4][4];
#pragma unroll
  for (int r = 0; r < 4; r++)
#pragma unroll
    for (int j = 0; j < 4; j++) acc[r][j] = pack2(0.f, 0.f);
#pragma unroll 4
  for (int k = 0; k < 64; k++) {
    float4 wr = *(const float4*)&WS[k * 96 + ty * 4];
    ull wp[4] = {pack2(wr.x, wr.x), pack2(wr.y, wr.y),
                 pack2(wr.z, wr.z), pack2(wr.w, wr.w)};
    ull xp2[4];
#pragma unroll
    for (int j = 0; j < 4; j++)
      xp2[j] = *(const ull*)&xs[k * 128 + 32 * j + (tx << 1)];
#pragma unroll
    for (int r = 0; r < 4; r++)
#pragma unroll
      for (int j = 0; j < 4; j++) acc[r][j] = ffma2(wp[r], xp2[j], acc[r][j]);
  }
#pragma unroll
  for (int r = 0; r < 4; r++) {
    int row = ty * 4 + r;
    int rr = (row < 48) ? row : row - 48;
    float* outp = (row < 48) ? fa : fb;
    float bias = (row < 48) ? ba[rr] : bb[rr];
    int k = rr >> 4, i = rr & 15;
    int base = (k * CN + n) * (ICN * TVN) + i * TVN + col0;
#pragma unroll
    for (int j = 0; j < 4; j++) {
      int cl = 32 * j + (tx << 1);
      if (col0 + cl < TVN) {
        float lo, hi;
        unpack2(acc[r][j], lo, hi);
        *(float2*)&outp[base + cl] = make_float2(lo + bias, hi + bias);
      }
    }
  }
}

// ---------------------------------------------------------------------------
// K2: S = softmax_v((fa^T fb)/4800) + (adj+PA)
// ---------------------------------------------------------------------------
__global__ __launch_bounds__(224) void k_S(
    const float* __restrict__ adj, const float* __restrict__ PA,
    const float* __restrict__ fa, const float* __restrict__ fb,
    float* __restrict__ Sout) {
  int k = blockIdx.x, n = blockIdx.y;
  __shared__ float sfa[1600], sfb[1600];
  __shared__ float sP[8 * 625];
  __shared__ float sS[625];
  __shared__ float smx[25], sinv[25];
  const float* fap = fa + (k * CN + n) * (ICN * TVN);
  const float* fbp = fb + (k * CN + n) * (ICN * TVN);
  int tid = threadIdx.x;
  float acc[25];
#pragma unroll
  for (int q = 0; q < 25; q++) acc[q] = 0.f;
  int tile = tid % 25, es = tid / 25;
  int vt = (tile / 5) * 5, wt = (tile % 5) * 5;
  for (int ch = 0; ch < 75; ch++) {
    __syncthreads();
    int d0 = ch * 64;
    for (int m = tid; m < 1600; m += 224) {
      int e = m / 25, vv = m - e * 25;
      int d = d0 + e;
      int i = d / 300, t = d - i * 300;
      int addr = i * TVN + t * 25 + vv;
      sfa[m] = fap[addr];
      sfb[m] = fbp[addr];
    }
    __syncthreads();
    if (tid < 200) {
#pragma unroll
      for (int ee = 0; ee < 8; ee++) {
        int e = es * 8 + ee;
        float av[5], bv[5];
#pragma unroll
        for (int q = 0; q < 5; q++) { av[q] = sfa[e * 25 + vt + q]; bv[q] = sfb[e * 25 + wt + q]; }
#pragma unroll
        for (int a2 = 0; a2 < 5; a2++)
#pragma unroll
          for (int b2 = 0; b2 < 5; b2++) acc[a2 * 5 + b2] += av[a2] * bv[b2];
      }
    }
  }
  __syncthreads();
  if (tid < 200) {
#pragma unroll
    for (int a2 = 0; a2 < 5; a2++)
#pragma unroll
      for (int b2 = 0; b2 < 5; b2++)
        sP[es * 625 + (vt + a2) * 25 + (wt + b2)] = acc[a2 * 5 + b2];
  }
  __syncthreads();
  for (int m = tid; m < 625; m += 224) {
    float s = 0.f;
#pragma unroll
    for (int e = 0; e < 8; e++) s += sP[e * 625 + m];
    sS[m] = s * (1.0f / 4800.0f);
  }
  __syncthreads();
  if (tid < 25) {
    float mx = -1e30f;
    for (int v = 0; v < 25; v++) mx = fmaxf(mx, sS[v * 25 + tid]);
    float sm = 0.f;
    for (int v = 0; v < 25; v++) sm += expf(sS[v * 25 + tid] - mx);
    smx[tid] = mx;
    sinv[tid] = 1.f / sm;
  }
  __syncthreads();
  float* so = Sout + (k * CN + n) * 625;
  for (int m = tid; m < 625; m += 224) {
    int w = m % 25;
    so[m] = expf(sS[m] - smx[w]) * sinv[w] + adj[k * 625 + m] + PA[k * 625 + m];
  }
}

// ---------------------------------------------------------------------------
// K3: fused Z + Wd-GEMM + BN-stats partials.
// smem floats: WdTs 4096 | Ss 1875 | xs 9600 | Zk 10240 | sred 128
// ---------------------------------------------------------------------------
#define ZS_WD 0
#define ZS_SS 4096
#define ZS_XS 5972
#define ZS_ZK 15572
#define ZS_PS 25812
#define ZS_TOT 25940

__global__ __launch_bounds__(256, 2) void k_zyg(
    const float* __restrict__ x, const float* __restrict__ Sbuf,
    const float* __restrict__ wdT, float* __restrict__ y1,
    float* __restrict__ ps1, float* __restrict__ ps2) {
  extern __shared__ __align__(16) float sm[];
  float* WdTs = sm + ZS_WD;
  float* Ss   = sm + ZS_SS;
  float* xs   = sm + ZS_XS;
  float* Zk   = sm + ZS_ZK;
  float* sred = sm + ZS_PS;  // 128 floats
  int n = blockIdx.y, t0 = blockIdx.x * 6;
  int col0 = t0 * 25;  // 150-aligned (even)
  int tid = threadIdx.x;
  int bid = n * 50 + blockIdx.x;
  for (int m = tid; m < 1875; m += 256) {
    int k = m / 625;
    Ss[m] = Sbuf[(k * CN + n) * 625 + (m - k * 625)];
  }
  const float* xp = x + n * (CC * TVN) + col0;
  for (int m = tid; m < 9600; m += 256) {
    int c = m / 150, col = m - c * 150;
    xs[m] = xp[c * TVN + col];
  }
  for (int m = tid; m < 10240; m += 256) Zk[m] = 0.f;

  int ty = tid >> 4, tx = tid & 15;  // 16 x 16 for Phase B
  ull acc[4][5];
#pragma unroll
  for (int r = 0; r < 4; r++)
#pragma unroll
    for (int j = 0; j < 5; j++) acc[r][j] = pack2(0.f, 0.f);

  int cgA = 0, ttA = 0, wtA = 0;
  bool doA = (tid < 240);
  if (doA) {
    int r = tid;
    cgA = r / 30;
    int r2 = r - cgA * 30;
    ttA = r2 / 5;
    wtA = r2 - ttA * 5;
  }
  int cbA = cgA * 8, w0A = wtA * 5;

  for (int k = 0; k < 3; k++) {
    __syncthreads();
    for (int m = tid; m < 4096; m += 256) WdTs[m] = wdT[k * 4096 + m];
    if (doA) {
      const float* sp = Ss + k * 625;
      float a2[8][5];
#pragma unroll
      for (int ci = 0; ci < 8; ci++)
#pragma unroll
        for (int wi = 0; wi < 5; wi++) a2[ci][wi] = 0.f;
      for (int v = 0; v < 25; v++) {
        float xv[8], sv[5];
#pragma unroll
        for (int ci = 0; ci < 8; ci++) xv[ci] = xs[(cbA + ci) * 150 + ttA * 25 + v];
#pragma unroll
        for (int wi = 0; wi < 5; wi++) sv[wi] = sp[v * 25 + w0A + wi];
#pragma unroll
        for (int ci = 0; ci < 8; ci++)
#pragma unroll
          for (int wi = 0; wi < 5; wi++) a2[ci][wi] += xv[ci] * sv[wi];
      }
#pragma unroll
      for (int ci = 0; ci < 8; ci++)
#pragma unroll
        for (int wi = 0; wi < 5; wi++)
          Zk[(cbA + ci) * 160 + ttA * 25 + w0A + wi] = a2[ci][wi];
    }
    __syncthreads();
#pragma unroll 2
    for (int c = 0; c < 64; c++) {
      float4 wr = *(const float4*)&WdTs[c * 64 + ty * 4];
      ull wp[4] = {pack2(wr.x, wr.x), pack2(wr.y, wr.y),
                   pack2(wr.z, wr.z), pack2(wr.w, wr.w)};
      ull xp2[5];
#pragma unroll
      for (int j = 0; j < 5; j++)
        xp2[j] = *(const ull*)&Zk[c * 160 + 32 * j + (tx << 1)];
#pragma unroll
      for (int r = 0; r < 4; r++)
#pragma unroll
        for (int j = 0; j < 5; j++) acc[r][j] = ffma2(wp[r], xp2[j], acc[r][j]);
    }
  }
  float psum[4], psq[4];
#pragma unroll
  for (int r = 0; r < 4; r++) { psum[r] = 0.f; psq[r] = 0.f; }
#pragma unroll
  for (int r = 0; r < 4; r++) {
    int o = ty * 4 + r;
    int base = (n * CC + o) * TVN + col0;
#pragma unroll
    for (int j = 0; j < 5; j++) {
      int cl = 32 * j + (tx << 1);
      if (cl < 150) {
        float lo, hi;
        unpack2(acc[r][j], lo, hi);
        *(float2*)&y1[base + cl] = make_float2(lo, hi);
        psum[r] += lo + hi;
        psq[r] += lo * lo + hi * hi;
      }
    }
  }
  // reduce over the 16 tx lanes (xor offsets < 16 stay within half-warp)
#pragma unroll
  for (int r = 0; r < 4; r++) {
#pragma unroll
    for (int off = 8; off > 0; off >>= 1) {
      psum[r] += __shfl_xor_sync(0xffffffffu, psum[r], off);
      psq[r] += __shfl_xor_sync(0xffffffffu, psq[r], off);
    }
  }
  if (tx == 0) {
#pragma unroll
    for (int r = 0; r < 4; r++) {
      sred[ty * 4 + r] = psum[r];
      sred[64 + ty * 4 + r] = psq[r];
    }
  }
  __syncthreads();
  if (tid < 64) {
    ps1[tid * 3200 + bid] = sred[tid];
    ps2[tid * 3200 + bid] = sred[64 + tid];
  }
}

// ---------------------------------------------------------------------------
// K4: reduce per-block stats partials -> bnA/bnB  (grid 64, one block per o)
// ---------------------------------------------------------------------------
__global__ __launch_bounds__(256) void k_bnfinal2(
    const float* __restrict__ gamma, const float* __restrict__ beta,
    const float* __restrict__ p1, const float* __restrict__ p2, int np) {
  int o = blockIdx.x, tid = threadIdx.x;
  float a = 0.f, b = 0.f;
  for (int i = tid; i < np; i += 256) { a += p1[o * np + i]; b += p2[o * np + i]; }
  __shared__ float s1[256], s2[256];
  s1[tid] = a; s2[tid] = b;
  __syncthreads();
  for (int off = 128; off > 0; off >>= 1) {
    if (tid < off) { s1[tid] += s1[tid + off]; s2[tid] += s2[tid + off]; }
    __syncthreads();
  }
  if (tid == 0) {
    float inv = 1.0f / 480000.0f;
    float mu = s1[0] * inv;
    float var = s2[0] * inv - mu * mu;
    float A = gamma[o] * rsqrtf(var + EPSBN);
    g_bnA[o] = A;
    g_bnB[o] = beta[o] - mu * A;
  }
}

// ---------------------------------------------------------------------------
// K6: out = relu(A[o]*in + B[o] + x)  (final epilogue only)
// ---------------------------------------------------------------------------
__global__ __launch_bounds__(256) void k_addrelu(
    const float4* __restrict__ in, const float4* __restrict__ x,
    float4* __restrict__ out) {
  int i = blockIdx.x * 256 + threadIdx.x;
  int o = (i / 1875) & 63;
  float A = g_bnA[o], B = g_bnB[o];
  float4 v = in[i], xx = x[i], r;
  r.x = fmaxf(A * v.x + B + xx.x, 0.f);
  r.y = fmaxf(A * v.y + B + xx.y, 0.f);
  r.z = fmaxf(A * v.z + B + xx.z, 0.f);
  r.w = fmaxf(A * v.w + B + xx.w, 0.f);
  out[i] = r;
}

// ---------------------------------------------------------------------------
// K7: temporal conv, fused BN1+residual+ReLU on load, fused BN2 stats.
// x staged as duplicated (v,v) ull pairs -> broadcast LDS.64, no movs.
// Weights read as ulonglong2 from float4 rows -> (o,o+1),(o+2,o+3) pairs.
// ---------------------------------------------------------------------------
__global__ __launch_bounds__(512) void k_tcn(
    const float* __restrict__ y1, const float* __restrict__ x,
    const float* __restrict__ wtT, float* __restrict__ yt,
    float* __restrict__ pt1, float* __restrict__ pt2) {
  __shared__ __align__(16) ull y2dup[8 * 456];        // 29184 B
  __shared__ __align__(16) float Ws[4608];            // 18432 B
  __shared__ float sA[64], sB[64];
  __shared__ float sred1[64], sred2[64];
  int n = blockIdx.y, col0 = blockIdx.x * 256;
  int tid = threadIdx.x;
  int bid = n * 30 + blockIdx.x;
  if (tid < 64) { sA[tid] = g_bnA[tid]; sB[tid] = g_bnB[tid]; }
  int ty = tid >> 5, tx = tid & 31;
  int o0 = ty * 4;
  ull acc2[2][8];
#pragma unroll
  for (int p = 0; p < 2; p++)
#pragma unroll
    for (int q = 0; q < 8; q++) acc2[p][q] = pack2(0.f, 0.f);
  for (int cc = 0; cc < 8; cc++) {
    __syncthreads();
    for (int m = tid; m < 3648; m += 512) {
      int c = m / 456, lc = m - c * 456;
      int cg = cc * 8 + c;
      int gc = col0 - 100 + lc;
      float v = 0.f;
      if (gc >= 0 && gc < TVN) {
        int gidx = (n * CC + cg) * TVN + gc;
        v = fmaxf(sA[cg] * y1[gidx] + sB[cg] + x[gidx], 0.f);
      }
      y2dup[m] = pack2(v, v);
    }
    for (int m = tid; m < 4608; m += 512) Ws[m] = wtT[cc * 4608 + m];
    __syncthreads();
#pragma unroll
    for (int c = 0; c < 8; c++) {
      const ull* xrow = &y2dup[c * 456 + tx];
#pragma unroll
      for (int dt = 0; dt < 9; dt++) {
        ulonglong2 wv = *(const ulonglong2*)&Ws[(c * 9 + dt) * 64 + o0];
#pragma unroll
        for (int q = 0; q < 8; q++) {
          ull xb = xrow[dt * 25 + 32 * q];
          acc2[0][q] = ffma2(wv.x, xb, acc2[0][q]);
          acc2[1][q] = ffma2(wv.y, xb, acc2[1][q]);
        }
      }
    }
  }
  bool fast = (col0 + 256 <= TVN);
  float ps[4], pq[4];
#pragma unroll
  for (int r = 0; r < 4; r++) { ps[r] = 0.f; pq[r] = 0.f; }
#pragma unroll
  for (int p = 0; p < 2; p++) {
    int baseA = (n * CC + o0 + 2 * p) * TVN + col0 + tx;
    int baseB = (n * CC + o0 + 2 * p + 1) * TVN + col0 + tx;
#pragma unroll
    for (int q = 0; q < 8; q++) {
      float lo, hi;
      unpack2(acc2[p][q], lo, hi);
      if (fast || col0 + tx + 32 * q < TVN) {
        yt[baseA + 32 * q] = lo;
        yt[baseB + 32 * q] = hi;
        ps[2 * p] += lo; pq[2 * p] += lo * lo;
        ps[2 * p + 1] += hi; pq[2 * p + 1] += hi * hi;
      }
    }
  }
#pragma unroll
  for (int r = 0; r < 4; r++) {
#pragma unroll
    for (int off = 16; off > 0; off >>= 1) {
      ps[r] += __shfl_xor_sync(0xffffffffu, ps[r], off);
      pq[r] += __shfl_xor_sync(0xffffffffu, pq[r], off);
    }
  }
  if (tx == 0) {
#pragma unroll
    for (int r = 0; r < 4; r++) { sred1[o0 + r] = ps[r]; sred2[o0 + r] = pq[r]; }
  }
  __syncthreads();
  if (tid < 64) {
    pt1[tid * 1920 + bid] = sred1[tid];
    pt2[tid * 1920 + bid] = sred2[tid];
  }
}

__global__ void k_copyadj(const float* __restrict__ adj, float* __restrict__ out) {
  int i = blockIdx.x * 256 + threadIdx.x;
  if (i < 1875) out[30720000 + i] = adj[i];
}

extern "C" void kernel_launch(void* const* d_in, const int* in_sizes, int n_in,
                              void* d_out, int out_size) {
  const float* x   = (const float*)d_in[0];
  const float* adj = (const float*)d_in[1];
  const float* PA  = (const float*)d_in[2];
  const float* Wa  = (const float*)d_in[3];
  const float* ba  = (const float*)d_in[4];
  const float* Wb  = (const float*)d_in[5];
  const float* bb  = (const float*)d_in[6];
  const float* Wd  = (const float*)d_in[7];
  const float* g1  = (const float*)d_in[9];
  const float* b1  = (const float*)d_in[10];
  const float* Wt  = (const float*)d_in[11];
  const float* g2  = (const float*)d_in[13];
  const float* b2  = (const float*)d_in[14];
  float* out = (float*)d_out;

  float* sc = nullptr;
  cudaGetSymbolAddress((void**)&sc, g_scratch);
  float *ps1p, *ps2p, *pt1p, *pt2p;
  cudaGetSymbolAddress((void**)&ps1p, g_ps1);
  cudaGetSymbolAddress((void**)&ps2p, g_ps2);
  cudaGetSymbolAddress((void**)&pt1p, g_pt1);
  cudaGetSymbolAddress((void**)&pt2p, g_pt2);

  static int smem_set = 0;
  if (!smem_set) {
    cudaFuncSetAttribute(k_zyg, cudaFuncAttributeMaxDynamicSharedMemorySize,
                         ZS_TOT * 4);
    smem_set = 1;
  }

  k_prep<<<216, 256>>>(Wa, Wb, Wd, Wt, sc + OFF_W);

  dim3 gGemm(59, 64);
  k_fafb<<<gGemm, 384>>>(x, sc + OFF_W, ba, bb, sc + OFF_FA, sc + OFF_FB);
  dim3 gS(3, 64);
  k_S<<<gS, 224>>>(adj, PA, sc + OFF_FA, sc + OFF_FB, sc + OFF_S);
  dim3 gZY(50, 64);
  k_zyg<<<gZY, 256, ZS_TOT * 4>>>(x, sc + OFF_S, sc + OFF_W + 6144,
                                  sc + OFF_YG, ps1p, ps2p);
  k_bnfinal2<<<64, 256>>>(g1, b1, ps1p, ps2p, 3200);
  dim3 gT(30, 64);
  k_tcn<<<gT, 512>>>(sc + OFF_YG, x, sc + OFF_W + 18432, sc + OFF_Z,
                     pt1p, pt2p);
  k_bnfinal2<<<64, 256>>>(g2, b2, pt1p, pt2p, 1920);
  k_addrelu<<<30000, 256>>>((const float4*)(sc + OFF_Z), (const float4*)x,
                            (float4*)out);
  if (out_size > 30720000) k_copyadj<<<8, 256>>>(adj, out);
}

// round 12
// speedup vs baseline: 1.2938x; 1.2938x over previous
#include <cuda_runtime.h>
#include <math.h>

#define CN 64
#define CC 64
#define CT 300
#define CV 25
#define TVN 7500
#define ICN 16
#define EPSBN 1e-5f

typedef unsigned long long ull;

__device__ __forceinline__ ull ffma2(ull a, ull b, ull c) {
  ull d;
  asm("fma.rn.f32x2 %0, %1, %2, %3;" : "=l"(d) : "l"(a), "l"(b), "l"(c));
  return d;
}
__device__ __forceinline__ ull pack2(float lo, float hi) {
  ull d;
  asm("mov.b64 %0, {%1, %2};" : "=l"(d) : "f"(lo), "f"(hi));
  return d;
}
__device__ __forceinline__ void unpack2(ull v, float& lo, float& hi) {
  asm("mov.b64 {%0, %1}, %2;" : "=f"(lo), "=f"(hi) : "l"(v));
}

static const int OFF_FA = 0;          // 23,040,000
static const int OFF_FB = 23040000;   // 23,040,000
static const int OFF_S  = 46080000;   // 120,000
static const int OFF_Z  = 46200000;   // yt (30,720,000 used)
static const int OFF_YG = 138360000;  // 30,720,000
static const int OFF_W  = 169080000;  // transposed weights
__device__ float g_scratch[169140000];
__device__ float g_ps1[204800];   // zyg stats partials: [o][3200]
__device__ float g_ps2[204800];
__device__ float g_pt1[122880];   // tcn stats partials: [o][1920]
__device__ float g_pt2[122880];
__device__ float g_bnA[64];
__device__ float g_bnB[64];

// ---------------------------------------------------------------------------
// K0: weight transposes for coalesced tile loads
// ---------------------------------------------------------------------------
__global__ void k_prep(const float* __restrict__ Wa, const float* __restrict__ Wb,
                       const float* __restrict__ Wd, const float* __restrict__ Wt,
                       float* __restrict__ wout) {
  int idx = blockIdx.x * 256 + threadIdx.x;
  if (idx < 6144) {
    int c = idx / 96, row = idx - c * 96;
    wout[idx] = (row < 48) ? Wa[row * 64 + c] : Wb[(row - 48) * 64 + c];
  } else if (idx < 6144 + 12288) {
    int j = idx - 6144;
    int o = j & 63, kc = j >> 6;
    int k = kc >> 6, c = kc & 63;
    wout[idx] = Wd[k * 4096 + o * 64 + c];
  } else if (idx < 55296) {
    int j = idx - 18432;
    int o = j & 63, cdt = j >> 6;
    wout[idx] = Wt[o * 576 + cdt];
  }
}

// ---------------------------------------------------------------------------
// K1: fa/fb GEMM 96x64x128 per block; f32x2 packed column pairs
// ---------------------------------------------------------------------------
__global__ __launch_bounds__(384) void k_fafb(
    const float* __restrict__ x, const float* __restrict__ wabT,
    const float* __restrict__ ba, const float* __restrict__ bb,
    float* __restrict__ fa, float* __restrict__ fb) {
  __shared__ __align__(16) float WS[64 * 96];
  __shared__ __align__(16) float xs[64 * 128];
  int n = blockIdx.y, col0 = blockIdx.x * 128;
  int tid = threadIdx.x;
  for (int m = tid; m < 6144; m += 384) WS[m] = wabT[m];
  const float* xp = x + n * (CC * TVN);
  for (int m = tid; m < 8192; m += 384) {
    int c = m >> 7, col = m & 127;
    int g = col0 + col;
    xs[m] = (g < TVN) ? xp[c * TVN + g] : 0.f;
  }
  __syncthreads();
  int ty = tid >> 4, tx = tid & 15;  // 24 x 16
  ull acc[4][4];
#pragma unroll
  for (int r = 0; r < 4; r++)
#pragma unroll
    for (int j = 0; j < 4; j++) acc[r][j] = pack2(0.f, 0.f);
#pragma unroll 4
  for (int k = 0; k < 64; k++) {
    float4 wr = *(const float4*)&WS[k * 96 + ty * 4];
    ull wp[4] = {pack2(wr.x, wr.x), pack2(wr.y, wr.y),
                 pack2(wr.z, wr.z), pack2(wr.w, wr.w)};
    ull xp2[4];
#pragma unroll
    for (int j = 0; j < 4; j++)
      xp2[j] = *(const ull*)&xs[k * 128 + 32 * j + (tx << 1)];
#pragma unroll
    for (int r = 0; r < 4; r++)
#pragma unroll
      for (int j = 0; j < 4; j++) acc[r][j] = ffma2(wp[r], xp2[j], acc[r][j]);
  }
#pragma unroll
  for (int r = 0; r < 4; r++) {
    int row = ty * 4 + r;
    int rr = (row < 48) ? row : row - 48;
    float* outp = (row < 48) ? fa : fb;
    float bias = (row < 48) ? ba[rr] : bb[rr];
    int k = rr >> 4, i = rr & 15;
    int base = (k * CN + n) * (ICN * TVN) + i * TVN + col0;
#pragma unroll
    for (int j = 0; j < 4; j++) {
      int cl = 32 * j + (tx << 1);
      if (col0 + cl < TVN) {
        float lo, hi;
        unpack2(acc[r][j], lo, hi);
        *(float2*)&outp[base + cl] = make_float2(lo + bias, hi + bias);
      }
    }
  }
}

// ---------------------------------------------------------------------------
// K2: S = softmax_v((fa^T fb)/4800) + (adj+PA)
// ---------------------------------------------------------------------------
__global__ __launch_bounds__(224) void k_S(
    const float* __restrict__ adj, const float* __restrict__ PA,
    const float* __restrict__ fa, const float* __restrict__ fb,
    float* __restrict__ Sout) {
  int k = blockIdx.x, n = blockIdx.y;
  __shared__ float sfa[1600], sfb[1600];
  __shared__ float sP[8 * 625];
  __shared__ float sS[625];
  __shared__ float smx[25], sinv[25];
  const float* fap = fa + (k * CN + n) * (ICN * TVN);
  const float* fbp = fb + (k * CN + n) * (ICN * TVN);
  int tid = threadIdx.x;
  float acc[25];
#pragma unroll
  for (int q = 0; q < 25; q++) acc[q] = 0.f;
  int tile = tid % 25, es = tid / 25;
  int vt = (tile / 5) * 5, wt = (tile % 5) * 5;
  for (int ch = 0; ch < 75; ch++) {
    __syncthreads();
    int d0 = ch * 64;
    for (int m = tid; m < 1600; m += 224) {
      int e = m / 25, vv = m - e * 25;
      int d = d0 + e;
      int i = d / 300, t = d - i * 300;
      int addr = i * TVN + t * 25 + vv;
      sfa[m] = fap[addr];
      sfb[m] = fbp[addr];
    }
    __syncthreads();
    if (tid < 200) {
#pragma unroll
      for (int ee = 0; ee < 8; ee++) {
        int e = es * 8 + ee;
        float av[5], bv[5];
#pragma unroll
        for (int q = 0; q < 5; q++) { av[q] = sfa[e * 25 + vt + q]; bv[q] = sfb[e * 25 + wt + q]; }
#pragma unroll
        for (int a2 = 0; a2 < 5; a2++)
#pragma unroll
          for (int b2 = 0; b2 < 5; b2++) acc[a2 * 5 + b2] += av[a2] * bv[b2];
      }
    }
  }
  __syncthreads();
  if (tid < 200) {
#pragma unroll
    for (int a2 = 0; a2 < 5; a2++)
#pragma unroll
      for (int b2 = 0; b2 < 5; b2++)
        sP[es * 625 + (vt + a2) * 25 + (wt + b2)] = acc[a2 * 5 + b2];
  }
  __syncthreads();
  for (int m = tid; m < 625; m += 224) {
    float s = 0.f;
#pragma unroll
    for (int e = 0; e < 8; e++) s += sP[e * 625 + m];
    sS[m] = s * (1.0f / 4800.0f);
  }
  __syncthreads();
  if (tid < 25) {
    float mx = -1e30f;
    for (int v = 0; v < 25; v++) mx = fmaxf(mx, sS[v * 25 + tid]);
    float sm = 0.f;
    for (int v = 0; v < 25; v++) sm += expf(sS[v * 25 + tid] - mx);
    smx[tid] = mx;
    sinv[tid] = 1.f / sm;
  }
  __syncthreads();
  float* so = Sout + (k * CN + n) * 625;
  for (int m = tid; m < 625; m += 224) {
    int w = m % 25;
    so[m] = expf(sS[m] - smx[w]) * sinv[w] + adj[k * 625 + m] + PA[k * 625 + m];
  }
}

// ---------------------------------------------------------------------------
// K3: fused Z + Wd-GEMM + BN-stats partials.
// smem floats: WdTs 4096 | Ss 1875 | xs 9600 | Zk 10240 | sred 128
// ---------------------------------------------------------------------------
#define ZS_WD 0
#define ZS_SS 4096
#define ZS_XS 5972
#define ZS_ZK 15572
#define ZS_PS 25812
#define ZS_TOT 25940

__global__ __launch_bounds__(256, 2) void k_zyg(
    const float* __restrict__ x, const float* __restrict__ Sbuf,
    const float* __restrict__ wdT, float* __restrict__ y1,
    float* __restrict__ ps1, float* __restrict__ ps2) {
  extern __shared__ __align__(16) float sm[];
  float* WdTs = sm + ZS_WD;
  float* Ss   = sm + ZS_SS;
  float* xs   = sm + ZS_XS;
  float* Zk   = sm + ZS_ZK;
  float* sred = sm + ZS_PS;  // 128 floats
  int n = blockIdx.y, t0 = blockIdx.x * 6;
  int col0 = t0 * 25;  // 150-aligned (even)
  int tid = threadIdx.x;
  int bid = n * 50 + blockIdx.x;
  for (int m = tid; m < 1875; m += 256) {
    int k = m / 625;
    Ss[m] = Sbuf[(k * CN + n) * 625 + (m - k * 625)];
  }
  const float* xp = x + n * (CC * TVN) + col0;
  for (int m = tid; m < 9600; m += 256) {
    int c = m / 150, col = m - c * 150;
    xs[m] = xp[c * TVN + col];
  }
  for (int m = tid; m < 10240; m += 256) Zk[m] = 0.f;

  int ty = tid >> 4, tx = tid & 15;  // 16 x 16 for Phase B
  ull acc[4][5];
#pragma unroll
  for (int r = 0; r < 4; r++)
#pragma unroll
    for (int j = 0; j < 5; j++) acc[r][j] = pack2(0.f, 0.f);

  int cgA = 0, ttA = 0, wtA = 0;
  bool doA = (tid < 240);
  if (doA) {
    int r = tid;
    cgA = r / 30;
    int r2 = r - cgA * 30;
    ttA = r2 / 5;
    wtA = r2 - ttA * 5;
  }
  int cbA = cgA * 8, w0A = wtA * 5;

  for (int k = 0; k < 3; k++) {
    __syncthreads();
    for (int m = tid; m < 4096; m += 256) WdTs[m] = wdT[k * 4096 + m];
    if (doA) {
      const float* sp = Ss + k * 625;
      float a2[8][5];
#pragma unroll
      for (int ci = 0; ci < 8; ci++)
#pragma unroll
        for (int wi = 0; wi < 5; wi++) a2[ci][wi] = 0.f;
      for (int v = 0; v < 25; v++) {
        float xv[8], sv[5];
#pragma unroll
        for (int ci = 0; ci < 8; ci++) xv[ci] = xs[(cbA + ci) * 150 + ttA * 25 + v];
#pragma unroll
        for (int wi = 0; wi < 5; wi++) sv[wi] = sp[v * 25 + w0A + wi];
#pragma unroll
        for (int ci = 0; ci < 8; ci++)
#pragma unroll
          for (int wi = 0; wi < 5; wi++) a2[ci][wi] += xv[ci] * sv[wi];
      }
#pragma unroll
      for (int ci = 0; ci < 8; ci++)
#pragma unroll
        for (int wi = 0; wi < 5; wi++)
          Zk[(cbA + ci) * 160 + ttA * 25 + w0A + wi] = a2[ci][wi];
    }
    __syncthreads();
#pragma unroll 2
    for (int c = 0; c < 64; c++) {
      float4 wr = *(const float4*)&WdTs[c * 64 + ty * 4];
      ull wp[4] = {pack2(wr.x, wr.x), pack2(wr.y, wr.y),
                   pack2(wr.z, wr.z), pack2(wr.w, wr.w)};
      ull xp2[5];
#pragma unroll
      for (int j = 0; j < 5; j++)
        xp2[j] = *(const ull*)&Zk[c * 160 + 32 * j + (tx << 1)];
#pragma unroll
      for (int r = 0; r < 4; r++)
#pragma unroll
        for (int j = 0; j < 5; j++) acc[r][j] = ffma2(wp[r], xp2[j], acc[r][j]);
    }
  }
  float psum[4], psq[4];
#pragma unroll
  for (int r = 0; r < 4; r++) { psum[r] = 0.f; psq[r] = 0.f; }
#pragma unroll
  for (int r = 0; r < 4; r++) {
    int o = ty * 4 + r;
    int base = (n * CC + o) * TVN + col0;
#pragma unroll
    for (int j = 0; j < 5; j++) {
      int cl = 32 * j + (tx << 1);
      if (cl < 150) {
        float lo, hi;
        unpack2(acc[r][j], lo, hi);
        *(float2*)&y1[base + cl] = make_float2(lo, hi);
        psum[r] += lo + hi;
        psq[r] += lo * lo + hi * hi;
      }
    }
  }
#pragma unroll
  for (int r = 0; r < 4; r++) {
#pragma unroll
    for (int off = 8; off > 0; off >>= 1) {
      psum[r] += __shfl_xor_sync(0xffffffffu, psum[r], off);
      psq[r] += __shfl_xor_sync(0xffffffffu, psq[r], off);
    }
  }
  if (tx == 0) {
#pragma unroll
    for (int r = 0; r < 4; r++) {
      sred[ty * 4 + r] = psum[r];
      sred[64 + ty * 4 + r] = psq[r];
    }
  }
  __syncthreads();
  if (tid < 64) {
    ps1[tid * 3200 + bid] = sred[tid];
    ps2[tid * 3200 + bid] = sred[64 + tid];
  }
}

// ---------------------------------------------------------------------------
// K4: reduce per-block stats partials -> bnA/bnB  (grid 64, one block per o)
// ---------------------------------------------------------------------------
__global__ __launch_bounds__(256) void k_bnfinal2(
    const float* __restrict__ gamma, const float* __restrict__ beta,
    const float* __restrict__ p1, const float* __restrict__ p2, int np) {
  int o = blockIdx.x, tid = threadIdx.x;
  float a = 0.f, b = 0.f;
  for (int i = tid; i < np; i += 256) { a += p1[o * np + i]; b += p2[o * np + i]; }
  __shared__ float s1[256], s2[256];
  s1[tid] = a; s2[tid] = b;
  __syncthreads();
  for (int off = 128; off > 0; off >>= 1) {
    if (tid < off) { s1[tid] += s1[tid + off]; s2[tid] += s2[tid + off]; }
    __syncthreads();
  }
  if (tid == 0) {
    float inv = 1.0f / 480000.0f;
    float mu = s1[0] * inv;
    float var = s2[0] * inv - mu * mu;
    float A = gamma[o] * rsqrtf(var + EPSBN);
    g_bnA[o] = A;
    g_bnB[o] = beta[o] - mu * A;
  }
}

// ---------------------------------------------------------------------------
// K6: out = relu(A[o]*in + B[o] + x)  (final epilogue only)
// ---------------------------------------------------------------------------
__global__ __launch_bounds__(256) void k_addrelu(
    const float4* __restrict__ in, const float4* __restrict__ x,
    float4* __restrict__ out) {
  int i = blockIdx.x * 256 + threadIdx.x;
  int o = (i / 1875) & 63;
  float A = g_bnA[o], B = g_bnB[o];
  float4 v = in[i], xx = x[i], r;
  r.x = fmaxf(A * v.x + B + xx.x, 0.f);
  r.y = fmaxf(A * v.y + B + xx.y, 0.f);
  r.z = fmaxf(A * v.z + B + xx.z, 0.f);
  r.w = fmaxf(A * v.w + B + xx.w, 0.f);
  out[i] = r;
}

// ---------------------------------------------------------------------------
// K7: temporal conv, fused BN1+residual+ReLU on load, fused BN2 stats.
// R9 inner loop: scalar y2cs staging (4B/value, crossbar-friendly),
// weights packed via 2 movs, x broadcast via pack2 mov (alu pipe).
// ---------------------------------------------------------------------------
__global__ __launch_bounds__(512) void k_tcn(
    const float* __restrict__ y1, const float* __restrict__ x,
    const float* __restrict__ wtT, float* __restrict__ yt,
    float* __restrict__ pt1, float* __restrict__ pt2) {
  __shared__ __align__(16) float y2cs[8 * 456];
  __shared__ __align__(16) float Ws[4608];
  __shared__ float sA[64], sB[64];
  __shared__ float sred1[64], sred2[64];
  int n = blockIdx.y, col0 = blockIdx.x * 256;
  int tid = threadIdx.x;
  int bid = n * 30 + blockIdx.x;
  if (tid < 64) { sA[tid] = g_bnA[tid]; sB[tid] = g_bnB[tid]; }
  int ty = tid >> 5, tx = tid & 31;
  int o0 = ty * 4;
  ull acc2[2][8];
#pragma unroll
  for (int p = 0; p < 2; p++)
#pragma unroll
    for (int q = 0; q < 8; q++) acc2[p][q] = pack2(0.f, 0.f);
  for (int cc = 0; cc < 8; cc++) {
    __syncthreads();
    for (int m = tid; m < 3648; m += 512) {
      int c = m / 456, lc = m - c * 456;
      int cg = cc * 8 + c;
      int gc = col0 - 100 + lc;
      float v = 0.f;
      if (gc >= 0 && gc < TVN) {
        int gidx = (n * CC + cg) * TVN + gc;
        v = fmaxf(sA[cg] * y1[gidx] + sB[cg] + x[gidx], 0.f);
      }
      y2cs[m] = v;
    }
    for (int m = tid; m < 4608; m += 512) Ws[m] = wtT[cc * 4608 + m];
    __syncthreads();
#pragma unroll
    for (int c = 0; c < 8; c++) {
      const float* xrow = &y2cs[c * 456 + tx];
#pragma unroll
      for (int dt = 0; dt < 9; dt++) {
        float4 wr = *(const float4*)&Ws[(c * 9 + dt) * 64 + o0];
        ull wp0 = pack2(wr.x, wr.y);
        ull wp1 = pack2(wr.z, wr.w);
#pragma unroll
        for (int q = 0; q < 8; q++) {
          float xv = xrow[dt * 25 + 32 * q];
          ull xb = pack2(xv, xv);
          acc2[0][q] = ffma2(wp0, xb, acc2[0][q]);
          acc2[1][q] = ffma2(wp1, xb, acc2[1][q]);
        }
      }
    }
  }
  bool fast = (col0 + 256 <= TVN);
  float ps[4], pq[4];
#pragma unroll
  for (int r = 0; r < 4; r++) { ps[r] = 0.f; pq[r] = 0.f; }
#pragma unroll
  for (int p = 0; p < 2; p++) {
    int baseA = (n * CC + o0 + 2 * p) * TVN + col0 + tx;
    int baseB = (n * CC + o0 + 2 * p + 1) * TVN + col0 + tx;
#pragma unroll
    for (int q = 0; q < 8; q++) {
      float lo, hi;
      unpack2(acc2[p][q], lo, hi);
      if (fast || col0 + tx + 32 * q < TVN) {
        yt[baseA + 32 * q] = lo;
        yt[baseB + 32 * q] = hi;
        ps[2 * p] += lo; pq[2 * p] += lo * lo;
        ps[2 * p + 1] += hi; pq[2 * p + 1] += hi * hi;
      }
    }
  }
#pragma unroll
  for (int r = 0; r < 4; r++) {
#pragma unroll
    for (int off = 16; off > 0; off >>= 1) {
      ps[r] += __shfl_xor_sync(0xffffffffu, ps[r], off);
      pq[r] += __shfl_xor_sync(0xffffffffu, pq[r], off);
    }
  }
  if (tx == 0) {
#pragma unroll
    for (int r = 0; r < 4; r++) { sred1[o0 + r] = ps[r]; sred2[o0 + r] = pq[r]; }
  }
  __syncthreads();
  if (tid < 64) {
    pt1[tid * 1920 + bid] = sred1[tid];
    pt2[tid * 1920 + bid] = sred2[tid];
  }
}

__global__ void k_copyadj(const float* __restrict__ adj, float* __restrict__ out) {
  int i = blockIdx.x * 256 + threadIdx.x;
  if (i < 1875) out[30720000 + i] = adj[i];
}

extern "C" void kernel_launch(void* const* d_in, const int* in_sizes, int n_in,
                              void* d_out, int out_size) {
  const float* x   = (const float*)d_in[0];
  const float* adj = (const float*)d_in[1];
  const float* PA  = (const float*)d_in[2];
  const float* Wa  = (const float*)d_in[3];
  const float* ba  = (const float*)d_in[4];
  const float* Wb  = (const float*)d_in[5];
  const float* bb  = (const float*)d_in[6];
  const float* Wd  = (const float*)d_in[7];
  const float* g1  = (const float*)d_in[9];
  const float* b1  = (const float*)d_in[10];
  const float* Wt  = (const float*)d_in[11];
  const float* g2  = (const float*)d_in[13];
  const float* b2  = (const float*)d_in[14];
  float* out = (float*)d_out;

  float* sc = nullptr;
  cudaGetSymbolAddress((void**)&sc, g_scratch);
  float *ps1p, *ps2p, *pt1p, *pt2p;
  cudaGetSymbolAddress((void**)&ps1p, g_ps1);
  cudaGetSymbolAddress((void**)&ps2p, g_ps2);
  cudaGetSymbolAddress((void**)&pt1p, g_pt1);
  cudaGetSymbolAddress((void**)&pt2p, g_pt2);

  static int smem_set = 0;
  if (!smem_set) {
    cudaFuncSetAttribute(k_zyg, cudaFuncAttributeMaxDynamicSharedMemorySize,
                         ZS_TOT * 4);
    smem_set = 1;
  }

  k_prep<<<216, 256>>>(Wa, Wb, Wd, Wt, sc + OFF_W);

  dim3 gGemm(59, 64);
  k_fafb<<<gGemm, 384>>>(x, sc + OFF_W, ba, bb, sc + OFF_FA, sc + OFF_FB);
  dim3 gS(3, 64);
  k_S<<<gS, 224>>>(adj, PA, sc + OFF_FA, sc + OFF_FB, sc + OFF_S);
  dim3 gZY(50, 64);
  k_zyg<<<gZY, 256, ZS_TOT * 4>>>(x, sc + OFF_S, sc + OFF_W + 6144,
                                  sc + OFF_YG, ps1p, ps2p);
  k_bnfinal2<<<64, 256>>>(g1, b1, ps1p, ps2p, 3200);
  dim3 gT(30, 64);
  k_tcn<<<gT, 512>>>(sc + OFF_YG, x, sc + OFF_W + 18432, sc + OFF_Z,
                     pt1p, pt2p);
  k_bnfinal2<<<64, 256>>>(g2, b2, pt1p, pt2p, 1920);
  k_addrelu<<<30000, 256>>>((const float4*)(sc + OFF_Z), (const float4*)x,
                            (float4*)out);
  if (out_size > 30720000) k_copyadj<<<8, 256>>>(adj, out);
}

// round 13
// speedup vs baseline: 1.3402x; 1.0359x over previous
#include <cuda_runtime.h>
#include <math.h>

#define CN 64
#define CC 64
#define CT 300
#define CV 25
#define TVN 7500
#define ICN 16
#define EPSBN 1e-5f

typedef unsigned long long ull;

__device__ __forceinline__ ull ffma2(ull a, ull b, ull c) {
  ull d;
  asm("fma.rn.f32x2 %0, %1, %2, %3;" : "=l"(d) : "l"(a), "l"(b), "l"(c));
  return d;
}
__device__ __forceinline__ ull pack2(float lo, float hi) {
  ull d;
  asm("mov.b64 %0, {%1, %2};" : "=l"(d) : "f"(lo), "f"(hi));
  return d;
}
__device__ __forceinline__ void unpack2(ull v, float& lo, float& hi) {
  asm("mov.b64 {%0, %1}, %2;" : "=f"(lo), "=f"(hi) : "l"(v));
}

static const int OFF_FA = 0;          // 23,040,000
static const int OFF_FB = 23040000;   // 23,040,000
static const int OFF_S  = 46080000;   // 120,000
static const int OFF_Z  = 46200000;   // yt (30,720,000 used)
static const int OFF_YG = 138360000;  // 30,720,000
static const int OFF_W  = 169080000;  // transposed weights
__device__ float g_scratch[169140000];
__device__ float g_ps1[204800];   // zyg stats partials: [o][3200]
__device__ float g_ps2[204800];
__device__ float g_pt1[245760];   // tcn stats partials: [o][3840]
__device__ float g_pt2[245760];
__device__ float g_bnA[64];
__device__ float g_bnB[64];

// ---------------------------------------------------------------------------
// K0: weight transposes for coalesced tile loads
// ---------------------------------------------------------------------------
__global__ void k_prep(const float* __restrict__ Wa, const float* __restrict__ Wb,
                       const float* __restrict__ Wd, const float* __restrict__ Wt,
                       float* __restrict__ wout) {
  int idx = blockIdx.x * 256 + threadIdx.x;
  if (idx < 6144) {
    int c = idx / 96, row = idx - c * 96;
    wout[idx] = (row < 48) ? Wa[row * 64 + c] : Wb[(row - 48) * 64 + c];
  } else if (idx < 6144 + 12288) {
    int j = idx - 6144;
    int o = j & 63, kc = j >> 6;
    int k = kc >> 6, c = kc & 63;
    wout[idx] = Wd[k * 4096 + o * 64 + c];
  } else if (idx < 55296) {
    int j = idx - 18432;
    int o = j & 63, cdt = j >> 6;
    wout[idx] = Wt[o * 576 + cdt];
  }
}

// ---------------------------------------------------------------------------
// K1: fa/fb GEMM 96x64x128 per block; f32x2 packed column pairs
// ---------------------------------------------------------------------------
__global__ __launch_bounds__(384) void k_fafb(
    const float* __restrict__ x, const float* __restrict__ wabT,
    const float* __restrict__ ba, const float* __restrict__ bb,
    float* __restrict__ fa, float* __restrict__ fb) {
  __shared__ __align__(16) float WS[64 * 96];
  __shared__ __align__(16) float xs[64 * 128];
  int n = blockIdx.y, col0 = blockIdx.x * 128;
  int tid = threadIdx.x;
  for (int m = tid; m < 6144; m += 384) WS[m] = wabT[m];
  const float* xp = x + n * (CC * TVN);
  for (int m = tid; m < 8192; m += 384) {
    int c = m >> 7, col = m & 127;
    int g = col0 + col;
    xs[m] = (g < TVN) ? xp[c * TVN + g] : 0.f;
  }
  __syncthreads();
  int ty = tid >> 4, tx = tid & 15;  // 24 x 16
  ull acc[4][4];
#pragma unroll
  for (int r = 0; r < 4; r++)
#pragma unroll
    for (int j = 0; j < 4; j++) acc[r][j] = pack2(0.f, 0.f);
#pragma unroll 4
  for (int k = 0; k < 64; k++) {
    float4 wr = *(const float4*)&WS[k * 96 + ty * 4];
    ull wp[4] = {pack2(wr.x, wr.x), pack2(wr.y, wr.y),
                 pack2(wr.z, wr.z), pack2(wr.w, wr.w)};
    ull xp2[4];
#pragma unroll
    for (int j = 0; j < 4; j++)
      xp2[j] = *(const ull*)&xs[k * 128 + 32 * j + (tx << 1)];
#pragma unroll
    for (int r = 0; r < 4; r++)
#pragma unroll
      for (int j = 0; j < 4; j++) acc[r][j] = ffma2(wp[r], xp2[j], acc[r][j]);
  }
#pragma unroll
  for (int r = 0; r < 4; r++) {
    int row = ty * 4 + r;
    int rr = (row < 48) ? row : row - 48;
    float* outp = (row < 48) ? fa : fb;
    float bias = (row < 48) ? ba[rr] : bb[rr];
    int k = rr >> 4, i = rr & 15;
    int base = (k * CN + n) * (ICN * TVN) + i * TVN + col0;
#pragma unroll
    for (int j = 0; j < 4; j++) {
      int cl = 32 * j + (tx << 1);
      if (col0 + cl < TVN) {
        float lo, hi;
        unpack2(acc[r][j], lo, hi);
        *(float2*)&outp[base + cl] = make_float2(lo + bias, hi + bias);
      }
    }
  }
}

// ---------------------------------------------------------------------------
// K2: S = softmax_v((fa^T fb)/4800) + (adj+PA)
// ---------------------------------------------------------------------------
__global__ __launch_bounds__(224) void k_S(
    const float* __restrict__ adj, const float* __restrict__ PA,
    const float* __restrict__ fa, const float* __restrict__ fb,
    float* __restrict__ Sout) {
  int k = blockIdx.x, n = blockIdx.y;
  __shared__ float sfa[1600], sfb[1600];
  __shared__ float sP[8 * 625];
  __shared__ float sS[625];
  __shared__ float smx[25], sinv[25];
  const float* fap = fa + (k * CN + n) * (ICN * TVN);
  const float* fbp = fb + (k * CN + n) * (ICN * TVN);
  int tid = threadIdx.x;
  float acc[25];
#pragma unroll
  for (int q = 0; q < 25; q++) acc[q] = 0.f;
  int tile = tid % 25, es = tid / 25;
  int vt = (tile / 5) * 5, wt = (tile % 5) * 5;
  for (int ch = 0; ch < 75; ch++) {
    __syncthreads();
    int d0 = ch * 64;
    for (int m = tid; m < 1600; m += 224) {
      int e = m / 25, vv = m - e * 25;
      int d = d0 + e;
      int i = d / 300, t = d - i * 300;
      int addr = i * TVN + t * 25 + vv;
      sfa[m] = fap[addr];
      sfb[m] = fbp[addr];
    }
    __syncthreads();
    if (tid < 200) {
#pragma unroll
      for (int ee = 0; ee < 8; ee++) {
        int e = es * 8 + ee;
        float av[5], bv[5];
#pragma unroll
        for (int q = 0; q < 5; q++) { av[q] = sfa[e * 25 + vt + q]; bv[q] = sfb[e * 25 + wt + q]; }
#pragma unroll
        for (int a2 = 0; a2 < 5; a2++)
#pragma unroll
          for (int b2 = 0; b2 < 5; b2++) acc[a2 * 5 + b2] += av[a2] * bv[b2];
      }
    }
  }
  __syncthreads();
  if (tid < 200) {
#pragma unroll
    for (int a2 = 0; a2 < 5; a2++)
#pragma unroll
      for (int b2 = 0; b2 < 5; b2++)
        sP[es * 625 + (vt + a2) * 25 + (wt + b2)] = acc[a2 * 5 + b2];
  }
  __syncthreads();
  for (int m = tid; m < 625; m += 224) {
    float s = 0.f;
#pragma unroll
    for (int e = 0; e < 8; e++) s += sP[e * 625 + m];
    sS[m] = s * (1.0f / 4800.0f);
  }
  __syncthreads();
  if (tid < 25) {
    float mx = -1e30f;
    for (int v = 0; v < 25; v++) mx = fmaxf(mx, sS[v * 25 + tid]);
    float sm = 0.f;
    for (int v = 0; v < 25; v++) sm += expf(sS[v * 25 + tid] - mx);
    smx[tid] = mx;
    sinv[tid] = 1.f / sm;
  }
  __syncthreads();
  float* so = Sout + (k * CN + n) * 625;
  for (int m = tid; m < 625; m += 224) {
    int w = m % 25;
    so[m] = expf(sS[m] - smx[w]) * sinv[w] + adj[k * 625 + m] + PA[k * 625 + m];
  }
}

// ---------------------------------------------------------------------------
// K3: fused Z + Wd-GEMM + BN-stats partials.
// ---------------------------------------------------------------------------
#define ZS_WD 0
#define ZS_SS 4096
#define ZS_XS 5972
#define ZS_ZK 15572
#define ZS_PS 25812
#define ZS_TOT 25940

__global__ __launch_bounds__(256, 2) void k_zyg(
    const float* __restrict__ x, const float* __restrict__ Sbuf,
    const float* __restrict__ wdT, float* __restrict__ y1,
    float* __restrict__ ps1, float* __restrict__ ps2) {
  extern __shared__ __align__(16) float sm[];
  float* WdTs = sm + ZS_WD;
  float* Ss   = sm + ZS_SS;
  float* xs   = sm + ZS_XS;
  float* Zk   = sm + ZS_ZK;
  float* sred = sm + ZS_PS;  // 128 floats
  int n = blockIdx.y, t0 = blockIdx.x * 6;
  int col0 = t0 * 25;
  int tid = threadIdx.x;
  int bid = n * 50 + blockIdx.x;
  for (int m = tid; m < 1875; m += 256) {
    int k = m / 625;
    Ss[m] = Sbuf[(k * CN + n) * 625 + (m - k * 625)];
  }
  const float* xp = x + n * (CC * TVN) + col0;
  for (int m = tid; m < 9600; m += 256) {
    int c = m / 150, col = m - c * 150;
    xs[m] = xp[c * TVN + col];
  }
  for (int m = tid; m < 10240; m += 256) Zk[m] = 0.f;

  int ty = tid >> 4, tx = tid & 15;
  ull acc[4][5];
#pragma unroll
  for (int r = 0; r < 4; r++)
#pragma unroll
    for (int j = 0; j < 5; j++) acc[r][j] = pack2(0.f, 0.f);

  int cgA = 0, ttA = 0, wtA = 0;
  bool doA = (tid < 240);
  if (doA) {
    int r = tid;
    cgA = r / 30;
    int r2 = r - cgA * 30;
    ttA = r2 / 5;
    wtA = r2 - ttA * 5;
  }
  int cbA = cgA * 8, w0A = wtA * 5;

  for (int k = 0; k < 3; k++) {
    __syncthreads();
    for (int m = tid; m < 4096; m += 256) WdTs[m] = wdT[k * 4096 + m];
    if (doA) {
      const float* sp = Ss + k * 625;
      float a2[8][5];
#pragma unroll
      for (int ci = 0; ci < 8; ci++)
#pragma unroll
        for (int wi = 0; wi < 5; wi++) a2[ci][wi] = 0.f;
      for (int v = 0; v < 25; v++) {
        float xv[8], sv[5];
#pragma unroll
        for (int ci = 0; ci < 8; ci++) xv[ci] = xs[(cbA + ci) * 150 + ttA * 25 + v];
#pragma unroll
        for (int wi = 0; wi < 5; wi++) sv[wi] = sp[v * 25 + w0A + wi];
#pragma unroll
        for (int ci = 0; ci < 8; ci++)
#pragma unroll
          for (int wi = 0; wi < 5; wi++) a2[ci][wi] += xv[ci] * sv[wi];
      }
#pragma unroll
      for (int ci = 0; ci < 8; ci++)
#pragma unroll
        for (int wi = 0; wi < 5; wi++)
          Zk[(cbA + ci) * 160 + ttA * 25 + w0A + wi] = a2[ci][wi];
    }
    __syncthreads();
#pragma unroll 2
    for (int c = 0; c < 64; c++) {
      float4 wr = *(const float4*)&WdTs[c * 64 + ty * 4];
      ull wp[4] = {pack2(wr.x, wr.x), pack2(wr.y, wr.y),
                   pack2(wr.z, wr.z), pack2(wr.w, wr.w)};
      ull xp2[5];
#pragma unroll
      for (int j = 0; j < 5; j++)
        xp2[j] = *(const ull*)&Zk[c * 160 + 32 * j + (tx << 1)];
#pragma unroll
      for (int r = 0; r < 4; r++)
#pragma unroll
        for (int j = 0; j < 5; j++) acc[r][j] = ffma2(wp[r], xp2[j], acc[r][j]);
    }
  }
  float psum[4], psq[4];
#pragma unroll
  for (int r = 0; r < 4; r++) { psum[r] = 0.f; psq[r] = 0.f; }
#pragma unroll
  for (int r = 0; r < 4; r++) {
    int o = ty * 4 + r;
    int base = (n * CC + o) * TVN + col0;
#pragma unroll
    for (int j = 0; j < 5; j++) {
      int cl = 32 * j + (tx << 1);
      if (cl < 150) {
        float lo, hi;
        unpack2(acc[r][j], lo, hi);
        *(float2*)&y1[base + cl] = make_float2(lo, hi);
        psum[r] += lo + hi;
        psq[r] += lo * lo + hi * hi;
      }
    }
  }
#pragma unroll
  for (int r = 0; r < 4; r++) {
#pragma unroll
    for (int off = 8; off > 0; off >>= 1) {
      psum[r] += __shfl_xor_sync(0xffffffffu, psum[r], off);
      psq[r] += __shfl_xor_sync(0xffffffffu, psq[r], off);
    }
  }
  if (tx == 0) {
#pragma unroll
    for (int r = 0; r < 4; r++) {
      sred[ty * 4 + r] = psum[r];
      sred[64 + ty * 4 + r] = psq[r];
    }
  }
  __syncthreads();
  if (tid < 64) {
    ps1[tid * 3200 + bid] = sred[tid];
    ps2[tid * 3200 + bid] = sred[64 + tid];
  }
}

// ---------------------------------------------------------------------------
// K4: reduce per-block stats partials -> bnA/bnB
// ---------------------------------------------------------------------------
__global__ __launch_bounds__(256) void k_bnfinal2(
    const float* __restrict__ gamma, const float* __restrict__ beta,
    const float* __restrict__ p1, const float* __restrict__ p2, int np) {
  int o = blockIdx.x, tid = threadIdx.x;
  float a = 0.f, b = 0.f;
  for (int i = tid; i < np; i += 256) { a += p1[o * np + i]; b += p2[o * np + i]; }
  __shared__ float s1[256], s2[256];
  s1[tid] = a; s2[tid] = b;
  __syncthreads();
  for (int off = 128; off > 0; off >>= 1) {
    if (tid < off) { s1[tid] += s1[tid + off]; s2[tid] += s2[tid + off]; }
    __syncthreads();
  }
  if (tid == 0) {
    float inv = 1.0f / 480000.0f;
    float mu = s1[0] * inv;
    float var = s2[0] * inv - mu * mu;
    float A = gamma[o] * rsqrtf(var + EPSBN);
    g_bnA[o] = A;
    g_bnB[o] = beta[o] - mu * A;
  }
}

// ---------------------------------------------------------------------------
// K6: out = relu(A[o]*in + B[o] + x)
// ---------------------------------------------------------------------------
__global__ __launch_bounds__(256) void k_addrelu(
    const float4* __restrict__ in, const float4* __restrict__ x,
    float4* __restrict__ out) {
  int i = blockIdx.x * 256 + threadIdx.x;
  int o = (i / 1875) & 63;
  float A = g_bnA[o], B = g_bnB[o];
  float4 v = in[i], xx = x[i], r;
  r.x = fmaxf(A * v.x + B + xx.x, 0.f);
  r.y = fmaxf(A * v.y + B + xx.y, 0.f);
  r.z = fmaxf(A * v.z + B + xx.z, 0.f);
  r.w = fmaxf(A * v.w + B + xx.w, 0.f);
  out[i] = r;
}

// ---------------------------------------------------------------------------
// K7: temporal conv. 8o x 4col thread tile (2 column pairs), dual-parity
// staged tiles (y2e + y2o shifted by one) -> every tap is an aligned,
// conflict-free LDS.64. Fused BN1+residual+ReLU on load, fused BN2 stats.
// Dyn smem floats: y2e 3648 | y2o 3648 | Ws 4608 | sA 64 | sB 64 | sr 256
// ---------------------------------------------------------------------------
#define TS_Y2E 0
#define TS_Y2O 3648
#define TS_WS 7296
#define TS_SA 11904
#define TS_SB 11968
#define TS_SR1 12032
#define TS_SR2 12160
#define TS_TOT 12288

__global__ __launch_bounds__(512) void k_tcn(
    const float* __restrict__ y1, const float* __restrict__ x,
    const float* __restrict__ wtT, float* __restrict__ yt,
    float* __restrict__ pt1, float* __restrict__ pt2) {
  extern __shared__ __align__(16) float tsm[];
  float* y2e = tsm + TS_Y2E;
  float* y2o = tsm + TS_Y2O;
  float* Ws  = tsm + TS_WS;
  float* sA  = tsm + TS_SA;
  float* sB  = tsm + TS_SB;
  float* sr1 = tsm + TS_SR1;
  float* sr2 = tsm + TS_SR2;
  int n = blockIdx.y, col0 = blockIdx.x * 256;
  int tid = threadIdx.x;
  int bid = n * 30 + blockIdx.x;
  if (tid < 64) { sA[tid] = g_bnA[tid]; sB[tid] = g_bnB[tid]; }
  int wid = tid >> 5, tx = tid & 31;
  int og = wid >> 1, half = wid & 1;
  int o0 = og * 8;
  int cbase = half * 128 + (tx << 1);
  ull acc[8][2];
#pragma unroll
  for (int i = 0; i < 8; i++) { acc[i][0] = pack2(0.f, 0.f); acc[i][1] = pack2(0.f, 0.f); }
  for (int cc = 0; cc < 8; cc++) {
    __syncthreads();
    for (int m = tid; m < 3648; m += 512) {
      int c = m / 456, lc = m - c * 456;
      int cg = cc * 8 + c;
      int gc = col0 - 100 + lc;
      float v = 0.f;
      if (gc >= 0 && gc < TVN) {
        int gidx = (n * CC + cg) * TVN + gc;
        v = fmaxf(sA[cg] * y1[gidx] + sB[cg] + x[gidx], 0.f);
      }
      y2e[m] = v;
      if (lc > 0) y2o[m - 1] = v;
    }
    for (int m = tid; m < 4608; m += 512) Ws[m] = wtT[cc * 4608 + m];
    __syncthreads();
#pragma unroll
    for (int c = 0; c < 8; c++) {
      int rb = c * 456;
#pragma unroll
      for (int dt = 0; dt < 9; dt++) {
        const float* wrow = &Ws[(c * 9 + dt) * 64 + o0];
        float4 wa = *(const float4*)&wrow[0];
        float4 wb = *(const float4*)&wrow[4];
        ull wp[8] = {pack2(wa.x, wa.x), pack2(wa.y, wa.y),
                     pack2(wa.z, wa.z), pack2(wa.w, wa.w),
                     pack2(wb.x, wb.x), pack2(wb.y, wb.y),
                     pack2(wb.z, wb.z), pack2(wb.w, wb.w)};
        int loc = rb + cbase + 25 * dt;
        ull x0, x1;
        if (dt & 1) {
          x0 = *(const ull*)&y2o[loc - 1];
          x1 = *(const ull*)&y2o[loc + 63];
        } else {
          x0 = *(const ull*)&y2e[loc];
          x1 = *(const ull*)&y2e[loc + 64];
        }
#pragma unroll
        for (int i = 0; i < 8; i++) {
          acc[i][0] = ffma2(wp[i], x0, acc[i][0]);
          acc[i][1] = ffma2(wp[i], x1, acc[i][1]);
        }
      }
    }
  }
  float ps[8], pq[8];
#pragma unroll
  for (int i = 0; i < 8; i++) { ps[i] = 0.f; pq[i] = 0.f; }
#pragma unroll
  for (int i = 0; i < 8; i++) {
    int rowbase = (n * CC + o0 + i) * TVN;
#pragma unroll
    for (int j = 0; j < 2; j++) {
      int col = col0 + cbase + 64 * j;
      if (col < TVN) {
        float lo, hi;
        unpack2(acc[i][j], lo, hi);
        *(float2*)&yt[rowbase + col] = make_float2(lo, hi);
        ps[i] += lo + hi;
        pq[i] += lo * lo + hi * hi;
      }
    }
  }
#pragma unroll
  for (int i = 0; i < 8; i++) {
#pragma unroll
    for (int off = 16; off > 0; off >>= 1) {
      ps[i] += __shfl_xor_sync(0xffffffffu, ps[i], off);
      pq[i] += __shfl_xor_sync(0xffffffffu, pq[i], off);
    }
  }
  if (tx == 0) {
#pragma unroll
    for (int i = 0; i < 8; i++) {
      sr1[half * 64 + o0 + i] = ps[i];
      sr2[half * 64 + o0 + i] = pq[i];
    }
  }
  __syncthreads();
  if (tid < 128) {
    int o = tid & 63, hf = tid >> 6;
    pt1[o * 3840 + bid * 2 + hf] = sr1[hf * 64 + o];
    pt2[o * 3840 + bid * 2 + hf] = sr2[hf * 64 + o];
  }
}

__global__ void k_copyadj(const float* __restrict__ adj, float* __restrict__ out) {
  int i = blockIdx.x * 256 + threadIdx.x;
  if (i < 1875) out[30720000 + i] = adj[i];
}

extern "C" void kernel_launch(void* const* d_in, const int* in_sizes, int n_in,
                              void* d_out, int out_size) {
  const float* x   = (const float*)d_in[0];
  const float* adj = (const float*)d_in[1];
  const float* PA  = (const float*)d_in[2];
  const float* Wa  = (const float*)d_in[3];
  const float* ba  = (const float*)d_in[4];
  const float* Wb  = (const float*)d_in[5];
  const float* bb  = (const float*)d_in[6];
  const float* Wd  = (const float*)d_in[7];
  const float* g1  = (const float*)d_in[9];
  const float* b1  = (const float*)d_in[10];
  const float* Wt  = (const float*)d_in[11];
  const float* g2  = (const float*)d_in[13];
  const float* b2  = (const float*)d_in[14];
  float* out = (float*)d_out;

  float* sc = nullptr;
  cudaGetSymbolAddress((void**)&sc, g_scratch);
  float *ps1p, *ps2p, *pt1p, *pt2p;
  cudaGetSymbolAddress((void**)&ps1p, g_ps1);
  cudaGetSymbolAddress((void**)&ps2p, g_ps2);
  cudaGetSymbolAddress((void**)&pt1p, g_pt1);
  cudaGetSymbolAddress((void**)&pt2p, g_pt2);

  static int smem_set = 0;
  if (!smem_set) {
    cudaFuncSetAttribute(k_zyg, cudaFuncAttributeMaxDynamicSharedMemorySize,
                         ZS_TOT * 4);
    cudaFuncSetAttribute(k_tcn, cudaFuncAttributeMaxDynamicSharedMemorySize,
                         TS_TOT * 4);
    smem_set = 1;
  }

  k_prep<<<216, 256>>>(Wa, Wb, Wd, Wt, sc + OFF_W);

  dim3 gGemm(59, 64);
  k_fafb<<<gGemm, 384>>>(x, sc + OFF_W, ba, bb, sc + OFF_FA, sc + OFF_FB);
  dim3 gS(3, 64);
  k_S<<<gS, 224>>>(adj, PA, sc + OFF_FA, sc + OFF_FB, sc + OFF_S);
  dim3 gZY(50, 64);
  k_zyg<<<gZY, 256, ZS_TOT * 4>>>(x, sc + OFF_S, sc + OFF_W + 6144,
                                  sc + OFF_YG, ps1p, ps2p);
  k_bnfinal2<<<64, 256>>>(g1, b1, ps1p, ps2p, 3200);
  dim3 gT(30, 64);
  k_tcn<<<gT, 512, TS_TOT * 4>>>(sc + OFF_YG, x, sc + OFF_W + 18432, sc + OFF_Z,
                                 pt1p, pt2p);
  k_bnfinal2<<<64, 256>>>(g2, b2, pt1p, pt2p, 3840);
  k_addrelu<<<30000, 256>>>((const float4*)(sc + OFF_Z), (const float4*)x,
                            (float4*)out);
  if (out_size > 30720000) k_copyadj<<<8, 256>>>(adj, out);
}